// round 10
// baseline (speedup 1.0000x reference)
#include <cuda_runtime.h>

// PeakSense: out[b,p] = sum_i exp(-0.5*(mass[b,i]-mu[p])^2 * exp(-lv[p])) * iv[b,i],
// terms with arg < -10 dropped. Masses sorted per batch -> per-peak window.
//
// R10 = R8 (best: ncu 9.22us) with the remaining instruction fat removed:
//  - no in-loop predicate: [lo,hi) tracks the arg>=-10 boundary to ~0.002 mass
//    units; boundary terms weigh <= e^-10 ~ 4.5e-5 vs outputs ~10 -> ~1e-6 rel.
//    Loop body = LDS + LDG + FADD + 2xFMUL + MUFU.EX2 + FFMA (7 instr/elem).
//  - approx setup: sqrt.approx(20*exp(lv)) instead of libm sqrtf + fp div.
//  - unroll x4, 4 accumulators -> MLP 4 on iv global loads.
// Shape unchanged: 1024 CTAs, 8 lanes/peak, mass-only 16KB smem, branchless
// 12+1-step rank search (verified R7/R8).

#define PS_B 128
#define PS_L 4096
#define PS_N 256
#define GROUPS 8                          // blocks per batch
#define PEAKS_PER_BLOCK (PS_N / GROUPS)   // 32
#define LANES 8                           // lanes per peak
#define THREADS (PEAKS_PER_BLOCK * LANES) // 256
#define LOG2E 1.4426950408889634f

__device__ __forceinline__ float ex2_approx(float x) {
    float r;
    asm("ex2.approx.f32 %0, %1;" : "=f"(r) : "f"(x));
    return r;
}
__device__ __forceinline__ float sqrt_approx(float x) {
    float r;
    asm("sqrt.approx.f32 %0, %1;" : "=f"(r) : "f"(x));
    return r;
}

__global__ __launch_bounds__(THREADS)
void peaksense_kernel(const float* __restrict__ mu,
                      const float* __restrict__ lv,
                      const float* __restrict__ masses,
                      const float* __restrict__ intens,
                      float* __restrict__ out) {
    __shared__ float sm_mass[PS_L];       // 16 KB

    const int b    = blockIdx.y;
    const int tid  = threadIdx.x;
    const int p    = blockIdx.x * PEAKS_PER_BLOCK + (tid >> 3);
    const int q    = tid & 7;             // lane within peak group
    const int lane = tid & 31;

    // Stage this batch's masses into shared (float4, 4 per thread, MLP=4).
    {
        const float4* m4 = reinterpret_cast<const float4*>(masses + (size_t)b * PS_L);
        float4* s4 = reinterpret_cast<float4*>(sm_mass);
        #pragma unroll
        for (int i = tid; i < PS_L / 4; i += THREADS) s4[i] = m4[i];
    }

    const float* __restrict__ iv = intens + (size_t)b * PS_L;

    const float m  = mu[p];
    const float lj = lv[p];
    const float inv_s2 = __expf(-lj);      // 1/sigma^2 (MUFU path)
    // R^2 = 20/inv_s2 = 20*exp(lv). approx sqrt; tiny symmetric boundary error
    // is ~e^-10-weighted -> ~1e-6 rel. Slight inflation keeps superset bias.
    const float R   = sqrt_approx(20.0f * __expf(lj)) * 1.0002f + 1e-5f;
    const float lob = m - R;
    const float hib = m + R;

    __syncthreads();

    // Branchless rank search (verified). Lanes 0-3: first >= lob.
    // Lanes 4-7: first > hib. 12 unrolled steps + final correction.
    const bool  isLo   = (q < 4);
    const float target = isLo ? lob : hib;
    int pos = 0;
    #pragma unroll
    for (int s = PS_L / 2; s > 0; s >>= 1) {
        float v = sm_mass[pos + s - 1];
        bool adv = isLo ? (v < target) : (v <= target);
        pos += adv ? s : 0;
    }
    {
        float v = sm_mass[pos];
        bool adv = isLo ? (v < target) : (v <= target);
        pos += adv ? 1 : 0;
    }
    const int base = lane & ~7;           // first lane of this peak group
    const int lo = __shfl_sync(0xFFFFFFFF, pos, base + 0);
    const int hi = __shfl_sync(0xFFFFFFFF, pos, base + 4);

    // w = exp2(c2*d*d); no in-loop predicate (see header comment).
    const float c2 = -0.5f * inv_s2 * LOG2E;

    float acc0 = 0.0f, acc1 = 0.0f, acc2 = 0.0f, acc3 = 0.0f;
    int i = lo + q;
    #pragma unroll 1
    for (; i + 3 * LANES < hi; i += 4 * LANES) {
        float x0 = sm_mass[i];
        float x1 = sm_mass[i +     LANES];
        float x2 = sm_mass[i + 2 * LANES];
        float x3 = sm_mass[i + 3 * LANES];
        float y0 = iv[i];
        float y1 = iv[i +     LANES];
        float y2 = iv[i + 2 * LANES];
        float y3 = iv[i + 3 * LANES];
        float d0 = x0 - m, d1 = x1 - m, d2 = x2 - m, d3 = x3 - m;
        acc0 = fmaf(ex2_approx(c2 * d0 * d0), y0, acc0);
        acc1 = fmaf(ex2_approx(c2 * d1 * d1), y1, acc1);
        acc2 = fmaf(ex2_approx(c2 * d2 * d2), y2, acc2);
        acc3 = fmaf(ex2_approx(c2 * d3 * d3), y3, acc3);
    }
    #pragma unroll 3
    for (; i < hi; i += LANES) {
        float d = sm_mass[i] - m;
        acc0 = fmaf(ex2_approx(c2 * d * d), iv[i], acc0);
    }

    // Reduce the 8 lanes of this peak.
    float acc = (acc0 + acc1) + (acc2 + acc3);
    acc += __shfl_xor_sync(0xFFFFFFFF, acc, 1);
    acc += __shfl_xor_sync(0xFFFFFFFF, acc, 2);
    acc += __shfl_xor_sync(0xFFFFFFFF, acc, 4);

    if (q == 0) out[(size_t)b * PS_N + p] = acc;
}

extern "C" void kernel_launch(void* const* d_in, const int* in_sizes, int n_in,
                              void* d_out, int out_size) {
    const float* mu     = (const float*)d_in[0];
    const float* lv     = (const float*)d_in[1];
    const float* masses = (const float*)d_in[2];
    const float* intens = (const float*)d_in[3];
    float* out = (float*)d_out;

    dim3 grid(GROUPS, PS_B);
    peaksense_kernel<<<grid, THREADS>>>(mu, lv, masses, intens, out);
}